// round 9
// baseline (speedup 1.0000x reference)
#include <cuda_runtime.h>
#include <cooperative_groups.h>

namespace cg = cooperative_groups;

#define B 64
#define N 16384
#define M 64
#define FULLM 0xFFFFFFFFu

// scratch (device globals — no allocation allowed)
__device__ float g_s[B * N];       // exp(beta*cos) from k1
__device__ float g_part[B * 64];   // per-block partial sums of exp (k1 grid.x = 64)

// ---------------------------------------------------------------------------
// k1 (identical to R4/R8 best): exp(beta*cos) per row + deterministic
// per-block partial sum. 4 lanes/row, 4 rows/thread -> 16 LDG.128.CS in
// flight. Block = 256 thr -> 256 rows. Grid = (64, B).
// ---------------------------------------------------------------------------
__global__ __launch_bounds__(256) void k1_logits(
    const float* __restrict__ key,    // [B, M]
    const float* __restrict__ beta,   // [B, 1]
    const float* __restrict__ mem)    // [B, N, M]
{
    const int b    = blockIdx.y;
    const int tid  = threadIdx.x;
    const int l    = tid & 3;
    const int grp  = tid >> 2;
    const int row0 = blockIdx.x * 256;

    const float4* kp = reinterpret_cast<const float4*>(key + b * M);
    float4 k4[4];
#pragma unroll
    for (int j = 0; j < 4; ++j) k4[j] = kp[l + 4 * j];

    float ks = 0.0f;
#pragma unroll
    for (int j = 0; j < 4; ++j)
        ks += k4[j].x * k4[j].x + k4[j].y * k4[j].y
            + k4[j].z * k4[j].z + k4[j].w * k4[j].w;

    float4 m4[4][4];
#pragma unroll
    for (int u = 0; u < 4; ++u) {
        const int row = row0 + u * 64 + grp;
        const float4* mp = reinterpret_cast<const float4*>(
            mem + ((size_t)b * N + row) * M);
#pragma unroll
        for (int j = 0; j < 4; ++j) m4[u][j] = __ldcs(mp + l + 4 * j);
    }

    float dt[4] = {0.f, 0.f, 0.f, 0.f}, ms[4] = {0.f, 0.f, 0.f, 0.f};
#pragma unroll
    for (int u = 0; u < 4; ++u)
#pragma unroll
        for (int j = 0; j < 4; ++j) {
            dt[u] += k4[j].x * m4[u][j].x + k4[j].y * m4[u][j].y
                   + k4[j].z * m4[u][j].z + k4[j].w * m4[u][j].w;
            ms[u] += m4[u][j].x * m4[u][j].x + m4[u][j].y * m4[u][j].y
                   + m4[u][j].z * m4[u][j].z + m4[u][j].w * m4[u][j].w;
        }

#pragma unroll
    for (int off = 1; off <= 2; off <<= 1) {
        ks += __shfl_xor_sync(FULLM, ks, off);
#pragma unroll
        for (int u = 0; u < 4; ++u) {
            dt[u] += __shfl_xor_sync(FULLM, dt[u], off);
            ms[u] += __shfl_xor_sync(FULLM, ms[u], off);
        }
    }

    float esum = 0.0f;
    if (l == 0) {
        const float kn = sqrtf(ks);
        const float be = __ldg(beta + b);
#pragma unroll
        for (int u = 0; u < 4; ++u) {
            const int row = row0 + u * 64 + grp;
            const float denom = fmaxf(kn * sqrtf(ms[u]), 1e-8f);
            const float e = __expf(be * (dt[u] / denom));
            g_s[b * N + row] = e;
            esum += e;
        }
    }

    __shared__ float sred[8];
#pragma unroll
    for (int o = 16; o > 0; o >>= 1)
        esum += __shfl_xor_sync(FULLM, esum, o);
    if ((tid & 31) == 0) sred[tid >> 5] = esum;
    __syncthreads();
    if (tid == 0) {
        float s = 0.0f;
#pragma unroll
        for (int w = 0; w < 8; ++w) s += sred[w];
        g_part[b * 64 + blockIdx.x] = s;
    }
}

// ---------------------------------------------------------------------------
// k2: cluster-2 epilogue, 128 CTAs x 1024 thr (one full wave). Each CTA owns
// half a batch (8192 elems). Warp-contiguous layout: warp w owns float4s
// [w*64, w*64+64) of the half; lane l holds float4 k*32+l, k=0..1. All halos
// via register shuffles + 64-float smem warp edges; CTA/circular edges via 2
// scalar loads done by 2 threads. Exactly 4 LDG.128 + 2 STG.128 per thread.
// Renorm sum combined across the 2-CTA cluster via DSMEM in fixed rank order.
// ---------------------------------------------------------------------------
__global__ __launch_bounds__(1024) __cluster_dims__(2, 1, 1)
void k2_address(
    const float* __restrict__ gate,     // [B,1]
    const float* __restrict__ shift,    // [B,3]
    const float* __restrict__ sharpen,  // [B,1]
    const float* __restrict__ last,     // [B,N]
    float* __restrict__ out)            // [B,N]
{
    cg::cluster_group cluster = cg::this_cluster();

    const int b    = blockIdx.x >> 1;
    const int h    = blockIdx.x & 1;     // batch half (== cluster rank)
    const int tid  = threadIdx.x;
    const int warp = tid >> 5;
    const int lane = tid & 31;

    __shared__ float sred[32];
    __shared__ float sS;
    __shared__ float edgeL[32];
    __shared__ float edgeR[32];
    __shared__ float sCtaL, sCtaR;
    __shared__ float cpsum;              // DSMEM target

    // ---- softmax denominator from k1 partials (warp 0, overlapped) ----
    if (warp == 0) {
        float S = g_part[b * 64 + lane] + g_part[b * 64 + 32 + lane];
#pragma unroll
        for (int o = 16; o > 0; o >>= 1)
            S += __shfl_xor_sync(FULLM, S, o);
        if (lane == 0) sS = S;
    }

    // ---- vector loads: 2 float4 of exp + 2 of last (coalesced) ----
    const int base4 = (b << 12) + (h << 11) + (warp << 6);  // float4 units
    const float4* sp4 = reinterpret_cast<const float4*>(g_s);
    const float4* lp4 = reinterpret_cast<const float4*>(last);
    float4 e4[2], a4[2];
#pragma unroll
    for (int k = 0; k < 2; ++k) {
        e4[k] = sp4[base4 + k * 32 + lane];
        a4[k] = lp4[base4 + k * 32 + lane];
    }
    __syncthreads();  // sS ready

    const float g  = __ldg(gate + b);
    const float gS = g / sS;
    const float og = 1.0f - g;
    const float s0 = __ldg(shift + b * 3 + 0);
    const float s1 = __ldg(shift + b * 3 + 1);
    const float s2 = __ldg(shift + b * 3 + 2);
    const float sh = __ldg(sharpen + b);

    // ---- gate interpolation in registers ----
    float4 w4[2];
#pragma unroll
    for (int k = 0; k < 2; ++k) {
        w4[k].x = fmaf(gS, e4[k].x, og * a4[k].x);
        w4[k].y = fmaf(gS, e4[k].y, og * a4[k].y);
        w4[k].z = fmaf(gS, e4[k].z, og * a4[k].z);
        w4[k].w = fmaf(gS, e4[k].w, og * a4[k].w);
    }

    // warp edges to smem; CTA edges (circular across halves/batch) by 2 threads
    if (lane == 0)  edgeL[warp] = w4[0].x;
    if (lane == 31) edgeR[warp] = w4[1].w;
    if (tid == 0) {
        const int i = b * N + (((h << 13) + N - 1) & (N - 1));
        sCtaL = fmaf(gS, g_s[i], og * last[i]);
    }
    if (tid == 1023) {
        const int i = b * N + (((h << 13) + 8192) & (N - 1));
        sCtaR = fmaf(gS, g_s[i], og * last[i]);
    }
    __syncthreads();

    const float wrapL = (warp == 0)  ? sCtaL : edgeR[warp - 1];
    const float wrapR = (warp == 31) ? sCtaR : edgeL[warp + 1];

    // ---- circular 3-tap conv + sharpen, halos via shuffles ----
    const float prevw = __shfl_sync(FULLM, w4[0].w, 31);  // lane31's k=0 .w
    const float nextx = __shfl_sync(FULLM, w4[1].x, 0);   // lane0's  k=1 .x

    float psum = 0.0f;
    float4 p4[2];
#pragma unroll
    for (int k = 0; k < 2; ++k) {
        float left = __shfl_up_sync(FULLM, w4[k].w, 1);
        if (lane == 0) left = (k == 0) ? wrapL : prevw;
        float right = __shfl_down_sync(FULLM, w4[k].x, 1);
        if (lane == 31) right = (k == 1) ? wrapR : nextx;

        p4[k].x = __powf(s0 * left    + s1 * w4[k].x + s2 * w4[k].y, sh);
        p4[k].y = __powf(s0 * w4[k].x + s1 * w4[k].y + s2 * w4[k].z, sh);
        p4[k].z = __powf(s0 * w4[k].y + s1 * w4[k].z + s2 * w4[k].w, sh);
        p4[k].w = __powf(s0 * w4[k].z + s1 * w4[k].w + s2 * right,  sh);
        psum += p4[k].x + p4[k].y + p4[k].z + p4[k].w;
    }

    // ---- CTA psum reduce (deterministic) ----
#pragma unroll
    for (int o = 16; o > 0; o >>= 1)
        psum += __shfl_xor_sync(FULLM, psum, o);
    if (lane == 0) sred[warp] = psum;
    __syncthreads();
    if (tid < 32) {
        float x = sred[tid];
#pragma unroll
        for (int o = 16; o > 0; o >>= 1)
            x += __shfl_xor_sync(FULLM, x, o);
        if (tid == 0) cpsum = x;
    }

    // ---- cluster combine via DSMEM (fixed rank order -> deterministic) ----
    cluster.sync();
    float P = 0.0f;
#pragma unroll
    for (int r = 0; r < 2; ++r)
        P += *cluster.map_shared_rank(&cpsum, r);
    cluster.sync();  // keep peer smem alive until both CTAs have read

    const float invP = 1.0f / (P + 1e-16f);

    float4* op4 = reinterpret_cast<float4*>(out);
#pragma unroll
    for (int k = 0; k < 2; ++k) {
        float4 p = p4[k];
        p.x *= invP; p.y *= invP; p.z *= invP; p.w *= invP;
        op4[base4 + k * 32 + lane] = p;
    }
}

extern "C" void kernel_launch(void* const* d_in, const int* in_sizes, int n_in,
                              void* d_out, int out_size) {
    const float* key     = (const float*)d_in[0];
    const float* beta    = (const float*)d_in[1];
    const float* gate    = (const float*)d_in[2];
    const float* shift   = (const float*)d_in[3];
    const float* sharpen = (const float*)d_in[4];
    const float* last    = (const float*)d_in[5];
    const float* mem     = (const float*)d_in[6];
    float* out = (float*)d_out;

    dim3 g1(N / 256, B);
    k1_logits<<<g1, 256>>>(key, beta, mem);
    k2_address<<<B * 2, 1024>>>(gate, shift, sharpen, last, out);
}

// round 10
// speedup vs baseline: 1.0048x; 1.0048x over previous
#include <cuda_runtime.h>
#include <cooperative_groups.h>

namespace cg = cooperative_groups;

#define B 64
#define N 16384
#define M 64
#define FULLM 0xFFFFFFFFu

// scratch (device globals — no allocation allowed)
__device__ float g_s[B * N];       // exp(beta*cos) from k1
__device__ float g_part[B * 64];   // per-block partial sums of exp (k1 grid.x = 64)

// ---------------------------------------------------------------------------
// k1: exp(beta*cos) per row + deterministic per-block partial sum.
// 4 lanes/row, 4 rows/thread -> 16 LDG.128.CS in flight. Also prefetches this
// block's slice of `last` into L2 so k2's reads hit L2.
// ---------------------------------------------------------------------------
__global__ __launch_bounds__(256) void k1_logits(
    const float* __restrict__ key,    // [B, M]
    const float* __restrict__ beta,   // [B, 1]
    const float* __restrict__ mem,    // [B, N, M]
    const float* __restrict__ last)   // [B, N] (prefetch only)
{
    const int b    = blockIdx.y;
    const int tid  = threadIdx.x;
    const int l    = tid & 3;
    const int grp  = tid >> 2;
    const int row0 = blockIdx.x * 256;

    // L2 prefetch of last[] (8 x 128B lines = this block's 1KB slice)
    if (tid < 8) {
        const float* lpre = last + (size_t)b * N + blockIdx.x * 256 + tid * 32;
        asm volatile("prefetch.global.L2 [%0];" :: "l"(lpre));
    }

    const float4* kp = reinterpret_cast<const float4*>(key + b * M);
    float4 k4[4];
#pragma unroll
    for (int j = 0; j < 4; ++j) k4[j] = kp[l + 4 * j];

    float ks = 0.0f;
#pragma unroll
    for (int j = 0; j < 4; ++j)
        ks += k4[j].x * k4[j].x + k4[j].y * k4[j].y
            + k4[j].z * k4[j].z + k4[j].w * k4[j].w;

    float4 m4[4][4];
#pragma unroll
    for (int u = 0; u < 4; ++u) {
        const int row = row0 + u * 64 + grp;
        const float4* mp = reinterpret_cast<const float4*>(
            mem + ((size_t)b * N + row) * M);
#pragma unroll
        for (int j = 0; j < 4; ++j) m4[u][j] = __ldcs(mp + l + 4 * j);
    }

    float dt[4] = {0.f, 0.f, 0.f, 0.f}, ms[4] = {0.f, 0.f, 0.f, 0.f};
#pragma unroll
    for (int u = 0; u < 4; ++u)
#pragma unroll
        for (int j = 0; j < 4; ++j) {
            dt[u] += k4[j].x * m4[u][j].x + k4[j].y * m4[u][j].y
                   + k4[j].z * m4[u][j].z + k4[j].w * m4[u][j].w;
            ms[u] += m4[u][j].x * m4[u][j].x + m4[u][j].y * m4[u][j].y
                   + m4[u][j].z * m4[u][j].z + m4[u][j].w * m4[u][j].w;
        }

#pragma unroll
    for (int off = 1; off <= 2; off <<= 1) {
        ks += __shfl_xor_sync(FULLM, ks, off);
#pragma unroll
        for (int u = 0; u < 4; ++u) {
            dt[u] += __shfl_xor_sync(FULLM, dt[u], off);
            ms[u] += __shfl_xor_sync(FULLM, ms[u], off);
        }
    }

    float esum = 0.0f;
    if (l == 0) {
        const float kn = sqrtf(ks);
        const float be = __ldg(beta + b);
#pragma unroll
        for (int u = 0; u < 4; ++u) {
            const int row = row0 + u * 64 + grp;
            const float denom = fmaxf(kn * sqrtf(ms[u]), 1e-8f);
            const float e = __expf(be * (dt[u] / denom));
            g_s[b * N + row] = e;
            esum += e;
        }
    }

    __shared__ float sred[8];
#pragma unroll
    for (int o = 16; o > 0; o >>= 1)
        esum += __shfl_xor_sync(FULLM, esum, o);
    if ((tid & 31) == 0) sred[tid >> 5] = esum;
    __syncthreads();
    if (tid == 0) {
        float s = 0.0f;
#pragma unroll
        for (int w = 0; w < 8; ++w) s += sred[w];
        g_part[b * 64 + blockIdx.x] = s;
    }
}

// ---------------------------------------------------------------------------
// k2: cluster-4 epilogue, 256 CTAs x 512 thr. CTA q of batch b owns elems
// [q*4096, (q+1)*4096). Warp w (of 16) owns 256 contiguous elems; lane l
// holds float4s w*64 + {0,32} + l -> exactly 4 LDG.128 + 2 STG.128 per
// thread. Halos via register shuffles + smem warp edges; CTA/circular edges
// via 2 threads' scalar loads (L2-hot). Renorm sum combined across the 4-CTA
// cluster via DSMEM in fixed rank order (deterministic).
// ---------------------------------------------------------------------------
__global__ __launch_bounds__(512) __cluster_dims__(4, 1, 1)
void k2_address(
    const float* __restrict__ gate,     // [B,1]
    const float* __restrict__ shift,    // [B,3]
    const float* __restrict__ sharpen,  // [B,1]
    const float* __restrict__ last,     // [B,N]
    float* __restrict__ out)            // [B,N]
{
    cg::cluster_group cluster = cg::this_cluster();

    const int b    = blockIdx.x >> 2;
    const int q    = blockIdx.x & 3;     // quarter of the batch (cluster rank)
    const int tid  = threadIdx.x;
    const int warp = tid >> 5;           // 0..15
    const int lane = tid & 31;

    __shared__ float sred[16];
    __shared__ float sS;
    __shared__ float edgeL[16];
    __shared__ float edgeR[16];
    __shared__ float sCtaL, sCtaR;
    __shared__ float cpsum;              // DSMEM target

    // ---- softmax denominator from k1 partials (warp 0, overlapped) ----
    if (warp == 0) {
        float S = g_part[b * 64 + lane] + g_part[b * 64 + 32 + lane];
#pragma unroll
        for (int o = 16; o > 0; o >>= 1)
            S += __shfl_xor_sync(FULLM, S, o);
        if (lane == 0) sS = S;
    }

    // ---- vector loads: 2 float4 of exp + 2 of last (coalesced, L2-hot) ----
    const int base4 = (b << 12) + (q << 10) + (warp << 6);  // float4 units
    const float4* sp4 = reinterpret_cast<const float4*>(g_s);
    const float4* lp4 = reinterpret_cast<const float4*>(last);
    float4 e4[2], a4[2];
#pragma unroll
    for (int k = 0; k < 2; ++k) {
        e4[k] = sp4[base4 + k * 32 + lane];
        a4[k] = lp4[base4 + k * 32 + lane];
    }
    __syncthreads();  // sS ready

    const float g  = __ldg(gate + b);
    const float gS = g / sS;
    const float og = 1.0f - g;
    const float s0 = __ldg(shift + b * 3 + 0);
    const float s1 = __ldg(shift + b * 3 + 1);
    const float s2 = __ldg(shift + b * 3 + 2);
    const float sh = __ldg(sharpen + b);

    // ---- gate interpolation in registers ----
    float4 w4[2];
#pragma unroll
    for (int k = 0; k < 2; ++k) {
        w4[k].x = fmaf(gS, e4[k].x, og * a4[k].x);
        w4[k].y = fmaf(gS, e4[k].y, og * a4[k].y);
        w4[k].z = fmaf(gS, e4[k].z, og * a4[k].z);
        w4[k].w = fmaf(gS, e4[k].w, og * a4[k].w);
    }

    // warp edges to smem; CTA edges (circular) by 2 threads (L2-hit loads)
    if (lane == 0)  edgeL[warp] = w4[0].x;
    if (lane == 31) edgeR[warp] = w4[1].w;
    if (tid == 0) {
        const int i = b * N + (((q << 12) + N - 1) & (N - 1));
        sCtaL = fmaf(gS, g_s[i], og * last[i]);
    }
    if (tid == 511) {
        const int i = b * N + (((q << 12) + 4096) & (N - 1));
        sCtaR = fmaf(gS, g_s[i], og * last[i]);
    }
    __syncthreads();

    const float wrapL = (warp == 0)  ? sCtaL : edgeR[warp - 1];
    const float wrapR = (warp == 15) ? sCtaR : edgeL[warp + 1];

    // ---- circular 3-tap conv + sharpen, halos via shuffles ----
    const float prevw = __shfl_sync(FULLM, w4[0].w, 31);  // lane31's k=0 .w
    const float nextx = __shfl_sync(FULLM, w4[1].x, 0);   // lane0's  k=1 .x

    float psum = 0.0f;
    float4 p4[2];
#pragma unroll
    for (int k = 0; k < 2; ++k) {
        float left = __shfl_up_sync(FULLM, w4[k].w, 1);
        if (lane == 0) left = (k == 0) ? wrapL : prevw;
        float right = __shfl_down_sync(FULLM, w4[k].x, 1);
        if (lane == 31) right = (k == 1) ? wrapR : nextx;

        p4[k].x = __powf(s0 * left    + s1 * w4[k].x + s2 * w4[k].y, sh);
        p4[k].y = __powf(s0 * w4[k].x + s1 * w4[k].y + s2 * w4[k].z, sh);
        p4[k].z = __powf(s0 * w4[k].y + s1 * w4[k].z + s2 * w4[k].w, sh);
        p4[k].w = __powf(s0 * w4[k].z + s1 * w4[k].w + s2 * right,  sh);
        psum += p4[k].x + p4[k].y + p4[k].z + p4[k].w;
    }

    // ---- CTA psum reduce (deterministic) ----
#pragma unroll
    for (int o = 16; o > 0; o >>= 1)
        psum += __shfl_xor_sync(FULLM, psum, o);
    if (lane == 0) sred[warp] = psum;
    __syncthreads();
    if (warp == 0) {
        float x = (lane < 16) ? sred[lane] : 0.0f;
#pragma unroll
        for (int o = 8; o > 0; o >>= 1)
            x += __shfl_xor_sync(FULLM, x, o);
        if (lane == 0) cpsum = x;
    }

    // ---- cluster combine via DSMEM (fixed rank order -> deterministic) ----
    cluster.sync();
    float P = 0.0f;
#pragma unroll
    for (int r = 0; r < 4; ++r)
        P += *cluster.map_shared_rank(&cpsum, r);
    cluster.sync();  // keep peer smem alive until all CTAs have read

    const float invP = 1.0f / (P + 1e-16f);

    float4* op4 = reinterpret_cast<float4*>(out);
#pragma unroll
    for (int k = 0; k < 2; ++k) {
        float4 p = p4[k];
        p.x *= invP; p.y *= invP; p.z *= invP; p.w *= invP;
        op4[base4 + k * 32 + lane] = p;
    }
}

extern "C" void kernel_launch(void* const* d_in, const int* in_sizes, int n_in,
                              void* d_out, int out_size) {
    const float* key     = (const float*)d_in[0];
    const float* beta    = (const float*)d_in[1];
    const float* gate    = (const float*)d_in[2];
    const float* shift   = (const float*)d_in[3];
    const float* sharpen = (const float*)d_in[4];
    const float* last    = (const float*)d_in[5];
    const float* mem     = (const float*)d_in[6];
    float* out = (float*)d_out;

    dim3 g1(N / 256, B);
    k1_logits<<<g1, 256>>>(key, beta, mem, last);
    k2_address<<<B * 4, 512>>>(gate, shift, sharpen, last, out);
}